// round 15
// baseline (speedup 1.0000x reference)
#include <cuda_runtime.h>
#include <cuda_fp16.h>
#include <cuda_bf16.h>
#include <cstdint>

// ---------------- problem constants ----------------
#define BB 32
#define NN 207
#define TT 24
#define EE 128
#define HH 8
#define HD 16
#define DMOUT 64
#define MM 32
#define G4 4                         // batches per fused block

#define OUT_N (BB * NN * TT * DMOUT)
#define ATTN_N (BB * NN * HH * TT * TT)

// P images: per (m,n): 128 k-rows x 128 n-cols fp16, swizzled (32KB)
__device__ __align__(16) __half g_Pimg[(size_t)3 * NN * 16384];
// W image: 128 k-rows x 64 n-cols fp16, 128B-row swizzle (16KB)
__device__ __align__(16) __half g_Wimg[8192];

// ---------------- helpers ----------------
__device__ __forceinline__ uint32_t smem_u32(const void* p) {
    uint32_t a;
    asm("{ .reg .u64 t; cvta.to.shared.u64 t, %1; cvt.u32.u64 %0, t; }" : "=r"(a) : "l"(p));
    return a;
}
// swizzled byte offset: 256B rows, 16B chunks ci 0..15
__device__ __forceinline__ uint32_t sw_off(int r, int ci) {
    return (uint32_t)r * 256u + (uint32_t)((ci ^ (r & 7)) << 4);
}
// swizzled byte offset: 128B rows, 16B chunks ci 0..7
__device__ __forceinline__ uint32_t sw_off64(int r, int ci) {
    return (uint32_t)r * 128u + (uint32_t)((ci ^ (r & 7)) << 4);
}
__device__ __forceinline__ void ldsm_x4(uint32_t* r, uint32_t addr) {
    asm volatile("ldmatrix.sync.aligned.m8n8.x4.shared.b16 {%0,%1,%2,%3}, [%4];"
                 : "=r"(r[0]), "=r"(r[1]), "=r"(r[2]), "=r"(r[3]) : "r"(addr));
}
__device__ __forceinline__ void ldsm_x4_t(uint32_t* r, uint32_t addr) {
    asm volatile("ldmatrix.sync.aligned.m8n8.x4.trans.shared.b16 {%0,%1,%2,%3}, [%4];"
                 : "=r"(r[0]), "=r"(r[1]), "=r"(r[2]), "=r"(r[3]) : "r"(addr));
}
__device__ __forceinline__ void mma_f16(float* d, const uint32_t* a, const uint32_t* b) {
    asm volatile("mma.sync.aligned.m16n8k16.row.col.f32.f16.f16.f32 "
                 "{%0,%1,%2,%3}, {%4,%5,%6,%7}, {%8,%9}, {%0,%1,%2,%3};"
                 : "+f"(d[0]), "+f"(d[1]), "+f"(d[2]), "+f"(d[3])
                 : "r"(a[0]), "r"(a[1]), "r"(a[2]), "r"(a[3]), "r"(b[0]), "r"(b[1]));
}
__device__ __forceinline__ void mma_bf16(float* d, const uint32_t* a, const uint32_t* b) {
    asm volatile("mma.sync.aligned.m16n8k16.row.col.f32.bf16.bf16.f32 "
                 "{%0,%1,%2,%3}, {%4,%5,%6,%7}, {%8,%9}, {%0,%1,%2,%3};"
                 : "+f"(d[0]), "+f"(d[1]), "+f"(d[2]), "+f"(d[3])
                 : "r"(a[0]), "r"(a[1]), "r"(a[2]), "r"(a[3]), "r"(b[0]), "r"(b[1]));
}
#define CP_ASYNC16(dst, src) \
    asm volatile("cp.async.cg.shared.global [%0], [%1], 16;" :: "r"(dst), "l"(src))
#define CP_COMMIT() asm volatile("cp.async.commit_group;")
#define CP_WAIT0()  asm volatile("cp.async.wait_group 0;")

__device__ __forceinline__ uint32_t pack_bf16(float x, float y) {
    __nv_bfloat16 h0 = __float2bfloat16(x);
    __nv_bfloat16 h1 = __float2bfloat16(y);
    return (uint32_t)__bfloat16_as_ushort(h0) | ((uint32_t)__bfloat16_as_ushort(h1) << 16);
}
__device__ __forceinline__ uint32_t pack_h2(float x, float y) {
    __half2 h = __float22half2_rn(make_float2(x, y));
    return *(uint32_t*)&h;
}

// ---------------- kernel 0: P images (all 3 matrices per block) + W image ----------------
#define PP_AL   16384
#define PP_B    32768
#define PP_IMG  65536
#define PP_SMEM 98304

__global__ __launch_bounds__(256, 2) void prep_P_kernel(
    const float* __restrict__ qp1, const float* __restrict__ qp2,
    const float* __restrict__ kp1, const float* __restrict__ kp2,
    const float* __restrict__ vp1, const float* __restrict__ vp2,
    const float* __restrict__ outW) {
    extern __shared__ float sm0[];
    char* smb = (char*)sm0;
    const uint32_t sbase = smem_u32(smb);

    const int n = blockIdx.x, tid = threadIdx.x;
    const int wid = tid >> 5, lane = tid & 31;
    const int wr = wid >> 2, wc = wid & 3;       // warp grid 2(M) x 4(N)
    const int grp = lane >> 2, tid4 = lane & 3;
    const int lq = lane & 7, qq = lane >> 3;

    if (n == 0) {
        char* gbase = (char*)g_Wimg;
#pragma unroll
        for (int it = 0; it < 16; it++) {
            int idx = it * 256 + tid;
            int k = idx >> 5, n2 = idx & 31;
            float2 v = *(const float2*)(outW + k * DMOUT + 2 * n2);
            uint32_t off = sw_off64(k, n2 >> 2) + (uint32_t)(n2 & 3) * 4u;
            *(uint32_t*)(gbase + off) = pack_h2(v.x, v.y);
        }
    }

    for (int m = 0; m < 3; m++) {
        if (m) __syncthreads();
        const float* p1 = (m == 0) ? qp1 : ((m == 1) ? kp1 : vp1);
        const float* p2 = (m == 0) ? qp2 : ((m == 1) ? kp2 : vp2);

        {
            const float* p1b = p1 + (size_t)n * 2048;
#pragma unroll
            for (int it = 0; it < 4; it++) {
                int idx2 = it * 256 + tid;
                int r = idx2 >> 4, cp = idx2 & 15;
                float2 v = *(const float2*)(p1b + r * 32 + 2 * cp);
                float hx = __bfloat162float(__float2bfloat16(v.x));
                float hy = __bfloat162float(__float2bfloat16(v.y));
                uint32_t off = sw_off(r, cp >> 2) + (uint32_t)(cp & 3) * 4u;
                *(uint32_t*)(smb + off)         = pack_bf16(v.x, v.y);
                *(uint32_t*)(smb + PP_AL + off) = pack_bf16(v.x - hx, v.y - hy);
            }
        }
        {
#pragma unroll
            for (int it = 0; it < 16; it++) {
                int idx2 = it * 256 + tid;
                int r = idx2 >> 7, cp = idx2 & 127;
                float2 v = *(const float2*)(p2 + r * 256 + 2 * cp);
                int jj = cp >> 6, lcp = cp & 63;
                float hx = __bfloat162float(__float2bfloat16(v.x));
                float hy = __bfloat162float(__float2bfloat16(v.y));
                uint32_t off = sw_off(r, lcp >> 2) + (uint32_t)(lcp & 3) * 4u;
                char* bb = smb + PP_B + jj * 16384;
                *(uint32_t*)(bb + off)        = pack_bf16(v.x, v.y);
                *(uint32_t*)(bb + 8192 + off) = pack_bf16(v.x - hx, v.y - hy);
            }
        }
        __syncthreads();

#pragma unroll
        for (int j = 0; j < 2; j++) {
            float acc[2][4][4];
#pragma unroll
            for (int mr = 0; mr < 2; mr++)
#pragma unroll
                for (int nt = 0; nt < 4; nt++)
#pragma unroll
                    for (int i = 0; i < 4; i++) acc[mr][nt][i] = 0.f;

            const uint32_t Ao[3] = {0u, PP_AL, 0u};
            const uint32_t Bo[3] = {0u, 0u, 8192u};
#pragma unroll
            for (int pass = 0; pass < 3; pass++) {
                const uint32_t aB = sbase + Ao[pass];
                const uint32_t bB = sbase + PP_B + (uint32_t)j * 16384u + Bo[pass];
#pragma unroll
                for (int kc = 0; kc < 2; kc++) {
                    uint32_t a[2][4];
#pragma unroll
                    for (int mr = 0; mr < 2; mr++) {
                        int r = wr * 32 + mr * 16 + lq + (qq & 1) * 8;
                        int ci = kc * 2 + (qq >> 1);
                        ldsm_x4(a[mr], aB + sw_off(r, ci));
                    }
                    uint32_t bf[4][2];
#pragma unroll
                    for (int p = 0; p < 2; p++) {
                        int r = kc * 16 + lq + (qq & 1) * 8;
                        int ci = wc * 4 + p * 2 + (qq >> 1);
                        uint32_t t4r[4];
                        ldsm_x4_t(t4r, bB + sw_off(r, ci));
                        bf[2 * p][0] = t4r[0]; bf[2 * p][1] = t4r[1];
                        bf[2 * p + 1][0] = t4r[2]; bf[2 * p + 1][1] = t4r[3];
                    }
#pragma unroll
                    for (int mr = 0; mr < 2; mr++)
#pragma unroll
                        for (int nt = 0; nt < 4; nt++)
                            mma_bf16(acc[mr][nt], a[mr], bf[nt]);
                }
            }
#pragma unroll
            for (int mr = 0; mr < 2; mr++) {
#pragma unroll
                for (int half = 0; half < 2; half++) {
                    int i_row = wr * 32 + mr * 16 + half * 8 + grp;
                    int k = 2 * i_row + j;
#pragma unroll
                    for (int nt = 0; nt < 4; nt++) {
                        int c = wc * 32 + nt * 8 + tid4 * 2;
                        *(uint32_t*)(smb + PP_IMG + sw_off(k, c >> 3) + tid4 * 4) =
                            pack_h2(acc[mr][nt][half * 2 + 0], acc[mr][nt][half * 2 + 1]);
                    }
                }
            }
        }
        __syncthreads();

        float4* dst = (float4*)(g_Pimg + (size_t)(m * NN + n) * 16384);
        const float4* src = (const float4*)(smb + PP_IMG);
#pragma unroll
        for (int i = 0; i < 8; i++)
            dst[i * 256 + tid] = src[i * 256 + tid];
    }
}

// ---------------- fused kernel: 4 batches, 512 threads, 2 CTAs/SM (32 warps) ----------------
// smem bytes per CTA (106,496):
//  [A 0..24576)      96x128 fp16 swizzled (X during proj; Q image -> sO after)
//  [B 24576..57344)  P image during proj; W image (16KB) after
//  [K 57344..81920)  96x128 fp16 swizzled K image
//  [V 81920..106496) 96x128 fp16 swizzled V image
#define OFF_Bb 24576
#define OFF_K  57344
#define OFF_V  81920
#define SMEMF_TOTAL 106496

__global__ __launch_bounds__(512, 2) void fused_kernel(
    const float* __restrict__ query, const float* __restrict__ key_,
    const float* __restrict__ value,
    const float* __restrict__ outb,
    float* __restrict__ out, float* __restrict__ attn_out, int write_attn) {
    extern __shared__ float smf[];
    char* smb = (char*)smf;
    const uint32_t sbase = smem_u32(smb);

    const int n = blockIdx.x;
    const int b0 = blockIdx.y * G4;
    const int tid = threadIdx.x, wid = tid >> 5, lane = tid & 31;
    const int grp = lane >> 2, tid4 = lane & 3;
    const int lq = lane & 7, qq = lane >> 3;

    // ===== three projections (M=96 = 4 batches x 24), order k, v, q =====
    // GEMM warp grid: 2(M) x 8(N): each warp 3 m-tiles x 2 n-tiles
    {
        const int wr = wid >> 3, wc = wid & 7;
        for (int mi = 0; mi < 3; mi++) {
            const int m = (mi + 1) % 3;               // 1, 2, 0
            if (mi) __syncthreads();
            {
                const char* bs = (const char*)(g_Pimg + (size_t)(m * NN + n) * 16384);
                uint32_t bd = sbase + OFF_Bb;
#pragma unroll
                for (int i = 0; i < 4; i++) {
                    int c = i * 512 + tid;
                    CP_ASYNC16(bd + c * 16, bs + c * 16);
                }
                CP_COMMIT();
            }
            {
                const float* x = (m == 0) ? query : ((m == 1) ? key_ : value);
#pragma unroll
                for (int it = 0; it < 6; it++) {
                    int idx = it * 512 + tid;          // 3072 float4 jobs
                    int r = idx >> 5, c4 = idx & 31;
                    int g = r / TT, t = r - g * TT;
                    float4 v = *(const float4*)(x + (((size_t)(b0 + g) * NN + n) * TT + t) * EE + 4 * c4);
                    uint2 pk;
                    pk.x = pack_h2(v.x, v.y);
                    pk.y = pack_h2(v.z, v.w);
                    uint32_t off = sw_off(r, c4 >> 1) + (uint32_t)(c4 & 1) * 8u;
                    *(uint2*)(smb + off) = pk;
                }
            }
            CP_WAIT0();
            __syncthreads();

            // GEMM 96 x 128 x 128
            float acc[3][2][4];
#pragma unroll
            for (int mr = 0; mr < 3; mr++)
#pragma unroll
                for (int nt = 0; nt < 2; nt++)
#pragma unroll
                    for (int i = 0; i < 4; i++) acc[mr][nt][i] = 0.f;

#pragma unroll
            for (int kc = 0; kc < 8; kc++) {
                uint32_t a[3][4];
#pragma unroll
                for (int mr = 0; mr < 3; mr++) {
                    int r = wr * 48 + mr * 16 + lq + (qq & 1) * 8;
                    int ci = kc * 2 + (qq >> 1);
                    ldsm_x4(a[mr], sbase + sw_off(r, ci));
                }
                uint32_t bf[2][2];
                {
                    int r = kc * 16 + lq + (qq & 1) * 8;
                    int ci = wc * 2 + (qq >> 1);
                    uint32_t t4r[4];
                    ldsm_x4_t(t4r, sbase + OFF_Bb + sw_off(r, ci));
                    bf[0][0] = t4r[0]; bf[0][1] = t4r[1];
                    bf[1][0] = t4r[2]; bf[1][1] = t4r[3];
                }
#pragma unroll
                for (int mr = 0; mr < 3; mr++)
#pragma unroll
                    for (int nt = 0; nt < 2; nt++)
                        mma_f16(acc[mr][nt], a[mr], bf[nt]);
            }

            // epilogue: relu -> swizzled image (A for q, K/V for k/v)
            const uint32_t obase = (m == 0) ? 0u : ((m == 1) ? (uint32_t)OFF_K : (uint32_t)OFF_V);
            if (m == 0) __syncthreads();   // all mma reads of A (X_query) done before overwrite
#pragma unroll
            for (int mr = 0; mr < 3; mr++) {
#pragma unroll
                for (int half = 0; half < 2; half++) {
                    int row = wr * 48 + mr * 16 + half * 8 + grp;
#pragma unroll
                    for (int nt = 0; nt < 2; nt++) {
                        int col = wc * 16 + nt * 8 + tid4 * 2;
                        *(uint32_t*)(smb + obase + sw_off(row, col >> 3) + (col & 7) * 2) =
                            pack_h2(fmaxf(acc[mr][nt][half * 2 + 0], 0.f),
                                    fmaxf(acc[mr][nt][half * 2 + 1], 0.f));
                    }
                }
            }
        }
    }
    __syncthreads();      // Q image + K,V images complete

    // W image async copy into B region (overlaps attention)
    {
        const char* ws = (const char*)g_Wimg;
#pragma unroll
        for (int i = 0; i < 2; i++) {
            int c = i * 512 + tid;
            CP_ASYNC16(sbase + OFF_Bb + c * 16, ws + c * 16);
        }
        CP_COMMIT();
    }

    // ===== tensor attention: 16 warps = (8 heads x 2 m-tiles), 4 reps over batches =====
    {
        const int h = wid >> 1, mt = wid & 1;
        const int ci_h = h * 2 + (qq >> 1);
#pragma unroll 1
        for (int g = 0; g < G4; g++) {
            const int rowb = g * TT;
            const long bn = (long)(b0 + g) * NN + n;

            // Q A-frag (this warp's m-tile) and K B-frags (3 n-tiles of s)
            uint32_t aq[4], kf[2][4];
            {
                int r = rowb + mt * 16 + lq + (qq & 1) * 8;
                if (r > 95) r = 95;
                ldsm_x4(aq, sbase + sw_off(r, ci_h));
            }
#pragma unroll
            for (int st = 0; st < 2; st++) {
                int r = rowb + st * 16 + lq + (qq & 1) * 8;
                if (r > 95) r = 95;
                ldsm_x4(kf[st], sbase + OFF_K + sw_off(r, ci_h));
            }
            uint32_t bK[3][2];
            bK[0][0] = kf[0][0]; bK[0][1] = kf[0][2];
            bK[1][0] = kf[0][1]; bK[1][1] = kf[0][3];
            bK[2][0] = kf[1][0]; bK[2][1] = kf[1][2];

            float S[3][4];
#pragma unroll
            for (int nt = 0; nt < 3; nt++) {
#pragma unroll
                for (int i = 0; i < 4; i++) S[nt][i] = 0.f;
                mma_f16(S[nt], aq, bK[nt]);
            }

            // softmax over s (cols), causal mask, in fragments
#pragma unroll
            for (int rh = 0; rh < 2; rh++) {
                int tloc = mt * 16 + grp + rh * 8;
                float x[3][2];
                float mx = -1e30f;
#pragma unroll
                for (int nt = 0; nt < 3; nt++)
#pragma unroll
                    for (int c = 0; c < 2; c++) {
                        int s = nt * 8 + 2 * tid4 + c;
                        bool ok = (tloc < TT) && (s <= tloc);
                        float v = ok ? S[nt][rh * 2 + c] * 0.25f : -1e30f;
                        x[nt][c] = v;
                        mx = fmaxf(mx, v);
                    }
                mx = fmaxf(mx, __shfl_xor_sync(0xffffffffu, mx, 1));
                mx = fmaxf(mx, __shfl_xor_sync(0xffffffffu, mx, 2));
                float sum = 0.f;
#pragma unroll
                for (int nt = 0; nt < 3; nt++)
#pragma unroll
                    for (int c = 0; c < 2; c++) {
                        float e = (x[nt][c] > -1e29f) ? __expf(x[nt][c] - mx) : 0.f;
                        x[nt][c] = e;
                        sum += e;
                    }
                sum += __shfl_xor_sync(0xffffffffu, sum, 1);
                sum += __shfl_xor_sync(0xffffffffu, sum, 2);
                float inv = (sum > 0.f) ? (1.f / sum) : 0.f;
#pragma unroll
                for (int nt = 0; nt < 3; nt++)
#pragma unroll
                    for (int c = 0; c < 2; c++)
                        S[nt][rh * 2 + c] = x[nt][c] * inv;
            }

            // write attn probabilities (fp32, valid rows only)
            if (write_attn) {
#pragma unroll
                for (int rh = 0; rh < 2; rh++) {
                    int tloc = mt * 16 + grp + rh * 8;
                    if (tloc < TT) {
                        float* ab = attn_out + (((bn * HH) + h) * TT + tloc) * TT + 2 * tid4;
#pragma unroll
                        for (int nt = 0; nt < 3; nt++)
                            *(float2*)(ab + nt * 8) =
                                make_float2(S[nt][rh * 2 + 0], S[nt][rh * 2 + 1]);
                    }
                }
            }

            // pack P to fp16 A-frags: [kchunk][4]
            uint32_t pa[2][4];
            pa[0][0] = pack_h2(S[0][0], S[0][1]);
            pa[0][1] = pack_h2(S[0][2], S[0][3]);
            pa[0][2] = pack_h2(S[1][0], S[1][1]);
            pa[0][3] = pack_h2(S[1][2], S[1][3]);
            pa[1][0] = pack_h2(S[2][0], S[2][1]);
            pa[1][1] = pack_h2(S[2][2], S[2][3]);
            pa[1][2] = 0u;
            pa[1][3] = 0u;

            // V B-frags (2 k-chunks x 2 d-tiles)
            uint32_t vf[2][4];
#pragma unroll
            for (int kc = 0; kc < 2; kc++) {
                int r = rowb + kc * 16 + lq + (qq & 1) * 8;
                if (r > 95) r = 95;
                ldsm_x4_t(vf[kc], sbase + OFF_V + sw_off(r, ci_h));
            }

            float O[2][4];
#pragma unroll
            for (int ntd = 0; ntd < 2; ntd++) {
#pragma unroll
                for (int i = 0; i < 4; i++) O[ntd][i] = 0.f;
#pragma unroll
                for (int kc = 0; kc < 2; kc++) {
                    uint32_t bv[2] = {vf[kc][ntd * 2], vf[kc][ntd * 2 + 1]};
                    mma_f16(O[ntd], pa[kc], bv);
                }
            }

            // sO as fp16 into A image (same cols this warp read Q from)
#pragma unroll
            for (int ntd = 0; ntd < 2; ntd++) {
                int row0 = rowb + mt * 16 + grp;
                int col = h * 16 + ntd * 8 + 2 * tid4;
                *(uint32_t*)(smb + sw_off(row0, col >> 3) + (col & 7) * 2) =
                    pack_h2(O[ntd][0], O[ntd][1]);
                if (mt == 0)
                    *(uint32_t*)(smb + sw_off(row0 + 8, col >> 3) + (col & 7) * 2) =
                        pack_h2(O[ntd][2], O[ntd][3]);
            }
        }
    }
    CP_WAIT0();
    __syncthreads();      // sO image complete, W image ready

    // ===== output projection: (96x128) @ (128x64) mma, warp grid 4(M) x 4(N) =====
    {
        const int wr = wid >> 2, wc = wid & 3;
        float acc[2][2][4];
#pragma unroll
        for (int mr = 0; mr < 2; mr++)
#pragma unroll
            for (int nt = 0; nt < 2; nt++)
#pragma unroll
                for (int i = 0; i < 4; i++) acc[mr][nt][i] = 0.f;

#pragma unroll
        for (int kc = 0; kc < 8; kc++) {
            uint32_t a[2][4];
#pragma unroll
            for (int mr = 0; mr < 2; mr++) {
                int r = wr * 32 + mr * 16 + lq + (qq & 1) * 8;   // rows 96..127 read junk (B region), discarded
                int ci = kc * 2 + (qq >> 1);
                ldsm_x4(a[mr], sbase + sw_off(r, ci));
            }
            uint32_t bf[2][2];
            {
                int r = kc * 16 + lq + (qq & 1) * 8;
                int ci = wc * 2 + (qq >> 1);
                uint32_t t4r[4];
                ldsm_x4_t(t4r, sbase + OFF_Bb + sw_off64(r, ci));
                bf[0][0] = t4r[0]; bf[0][1] = t4r[1];
                bf[1][0] = t4r[2]; bf[1][1] = t4r[3];
            }
#pragma unroll
            for (int mr = 0; mr < 2; mr++)
#pragma unroll
                for (int nt = 0; nt < 2; nt++)
                    mma_f16(acc[mr][nt], a[mr], bf[nt]);
        }

        float2 bias[2];
#pragma unroll
        for (int nt = 0; nt < 2; nt++) {
            int col = wc * 16 + nt * 8 + tid4 * 2;
            bias[nt] = make_float2(__ldg(outb + col), __ldg(outb + col + 1));
        }
#pragma unroll
        for (int mr = 0; mr < 2; mr++) {
#pragma unroll
            for (int half = 0; half < 2; half++) {
                int row = wr * 32 + mr * 16 + half * 8 + grp;
                if (row < 96) {
                    int g = row / TT, t2 = row - g * TT;
                    const long bn = (long)(b0 + g) * NN + n;
                    float* op = out + ((bn * TT) + t2) * DMOUT;
#pragma unroll
                    for (int nt = 0; nt < 2; nt++) {
                        int col = wc * 16 + nt * 8 + tid4 * 2;
                        *(float2*)(op + col) = make_float2(
                            fmaxf(acc[mr][nt][half * 2 + 0] + bias[nt].x, 0.f),
                            fmaxf(acc[mr][nt][half * 2 + 1] + bias[nt].y, 0.f));
                    }
                }
            }
        }
    }
}

// ---------------- launch ----------------
extern "C" void kernel_launch(void* const* d_in, const int* in_sizes, int n_in,
                              void* d_out, int out_size) {
    const float* query = (const float*)d_in[0];
    const float* key_  = (const float*)d_in[1];
    const float* value = (const float*)d_in[2];
    const float* qp1 = (const float*)d_in[4];
    const float* qp2 = (const float*)d_in[5];
    const float* kp1 = (const float*)d_in[6];
    const float* kp2 = (const float*)d_in[7];
    const float* vp1 = (const float*)d_in[8];
    const float* vp2 = (const float*)d_in[9];
    const float* outW = (const float*)d_in[10];
    const float* outb = (const float*)d_in[11];

    float* out = (float*)d_out;
    int write_attn = (out_size >= OUT_N + ATTN_N) ? 1 : 0;

    static int attr_done = 0;
    if (!attr_done) {
        cudaFuncSetAttribute(prep_P_kernel, cudaFuncAttributeMaxDynamicSharedMemorySize, PP_SMEM);
        cudaFuncSetAttribute(fused_kernel, cudaFuncAttributeMaxDynamicSharedMemorySize, SMEMF_TOTAL);
        attr_done = 1;
    }

    prep_P_kernel<<<NN, 256, PP_SMEM>>>(qp1, qp2, kp1, kp2, vp1, vp2, outW);
    fused_kernel<<<dim3(NN, BB / G4), 512, SMEMF_TOTAL>>>(
        query, key_, value, outb, out, out + OUT_N, write_attn);
}

// round 16
// speedup vs baseline: 1.0875x; 1.0875x over previous
#include <cuda_runtime.h>
#include <cuda_fp16.h>
#include <cuda_bf16.h>
#include <cstdint>

// ---------------- problem constants ----------------
#define BB 32
#define NN 207
#define TT 24
#define EE 128
#define HH 8
#define HD 16
#define DMOUT 64
#define MM 32
#define G4 4                         // batches per fused block

#define OUT_N (BB * NN * TT * DMOUT)
#define ATTN_N (BB * NN * HH * TT * TT)

// P images: per (m,n): 128 k-rows x 128 n-cols fp16, swizzled (32KB)
__device__ __align__(16) __half g_Pimg[(size_t)3 * NN * 16384];
// W image: 128 k-rows x 64 n-cols fp16, 128B-row swizzle (16KB)
__device__ __align__(16) __half g_Wimg[8192];

// ---------------- helpers ----------------
__device__ __forceinline__ uint32_t smem_u32(const void* p) {
    uint32_t a;
    asm("{ .reg .u64 t; cvta.to.shared.u64 t, %1; cvt.u32.u64 %0, t; }" : "=r"(a) : "l"(p));
    return a;
}
// swizzled byte offset: 256B rows, 16B chunks ci 0..15
__device__ __forceinline__ uint32_t sw_off(int r, int ci) {
    return (uint32_t)r * 256u + (uint32_t)((ci ^ (r & 7)) << 4);
}
// swizzled byte offset: 128B rows, 16B chunks ci 0..7
__device__ __forceinline__ uint32_t sw_off64(int r, int ci) {
    return (uint32_t)r * 128u + (uint32_t)((ci ^ (r & 7)) << 4);
}
__device__ __forceinline__ void ldsm_x4(uint32_t* r, uint32_t addr) {
    asm volatile("ldmatrix.sync.aligned.m8n8.x4.shared.b16 {%0,%1,%2,%3}, [%4];"
                 : "=r"(r[0]), "=r"(r[1]), "=r"(r[2]), "=r"(r[3]) : "r"(addr));
}
__device__ __forceinline__ void ldsm_x4_t(uint32_t* r, uint32_t addr) {
    asm volatile("ldmatrix.sync.aligned.m8n8.x4.trans.shared.b16 {%0,%1,%2,%3}, [%4];"
                 : "=r"(r[0]), "=r"(r[1]), "=r"(r[2]), "=r"(r[3]) : "r"(addr));
}
__device__ __forceinline__ void mma_f16(float* d, const uint32_t* a, const uint32_t* b) {
    asm volatile("mma.sync.aligned.m16n8k16.row.col.f32.f16.f16.f32 "
                 "{%0,%1,%2,%3}, {%4,%5,%6,%7}, {%8,%9}, {%0,%1,%2,%3};"
                 : "+f"(d[0]), "+f"(d[1]), "+f"(d[2]), "+f"(d[3])
                 : "r"(a[0]), "r"(a[1]), "r"(a[2]), "r"(a[3]), "r"(b[0]), "r"(b[1]));
}
__device__ __forceinline__ void mma_bf16(float* d, const uint32_t* a, const uint32_t* b) {
    asm volatile("mma.sync.aligned.m16n8k16.row.col.f32.bf16.bf16.f32 "
                 "{%0,%1,%2,%3}, {%4,%5,%6,%7}, {%8,%9}, {%0,%1,%2,%3};"
                 : "+f"(d[0]), "+f"(d[1]), "+f"(d[2]), "+f"(d[3])
                 : "r"(a[0]), "r"(a[1]), "r"(a[2]), "r"(a[3]), "r"(b[0]), "r"(b[1]));
}
#define CP_ASYNC16(dst, src) \
    asm volatile("cp.async.cg.shared.global [%0], [%1], 16;" :: "r"(dst), "l"(src))
#define CP_COMMIT() asm volatile("cp.async.commit_group;")
#define CP_WAIT0()  asm volatile("cp.async.wait_group 0;")
#define CP_WAIT1()  asm volatile("cp.async.wait_group 1;")

__device__ __forceinline__ uint32_t pack_bf16(float x, float y) {
    __nv_bfloat16 h0 = __float2bfloat16(x);
    __nv_bfloat16 h1 = __float2bfloat16(y);
    return (uint32_t)__bfloat16_as_ushort(h0) | ((uint32_t)__bfloat16_as_ushort(h1) << 16);
}
__device__ __forceinline__ uint32_t pack_h2(float x, float y) {
    __half2 h = __float22half2_rn(make_float2(x, y));
    return *(uint32_t*)&h;
}

// ---------------- kernel 0: P images (all 3 matrices per block) + W image ----------------
#define PP_AL   16384
#define PP_B    32768
#define PP_IMG  65536
#define PP_SMEM 98304

__global__ __launch_bounds__(256, 2) void prep_P_kernel(
    const float* __restrict__ qp1, const float* __restrict__ qp2,
    const float* __restrict__ kp1, const float* __restrict__ kp2,
    const float* __restrict__ vp1, const float* __restrict__ vp2,
    const float* __restrict__ outW) {
    extern __shared__ float sm0[];
    char* smb = (char*)sm0;
    const uint32_t sbase = smem_u32(smb);

    const int n = blockIdx.x, tid = threadIdx.x;
    const int wid = tid >> 5, lane = tid & 31;
    const int wr = wid >> 2, wc = wid & 3;       // warp grid 2(M) x 4(N)
    const int grp = lane >> 2, tid4 = lane & 3;
    const int lq = lane & 7, qq = lane >> 3;

    if (n == 0) {
        char* gbase = (char*)g_Wimg;
#pragma unroll
        for (int it = 0; it < 16; it++) {
            int idx = it * 256 + tid;
            int k = idx >> 5, n2 = idx & 31;
            float2 v = *(const float2*)(outW + k * DMOUT + 2 * n2);
            uint32_t off = sw_off64(k, n2 >> 2) + (uint32_t)(n2 & 3) * 4u;
            *(uint32_t*)(gbase + off) = pack_h2(v.x, v.y);
        }
    }

    for (int m = 0; m < 3; m++) {
        if (m) __syncthreads();
        const float* p1 = (m == 0) ? qp1 : ((m == 1) ? kp1 : vp1);
        const float* p2 = (m == 0) ? qp2 : ((m == 1) ? kp2 : vp2);

        {
            const float* p1b = p1 + (size_t)n * 2048;
#pragma unroll
            for (int it = 0; it < 4; it++) {
                int idx2 = it * 256 + tid;
                int r = idx2 >> 4, cp = idx2 & 15;
                float2 v = *(const float2*)(p1b + r * 32 + 2 * cp);
                float hx = __bfloat162float(__float2bfloat16(v.x));
                float hy = __bfloat162float(__float2bfloat16(v.y));
                uint32_t off = sw_off(r, cp >> 2) + (uint32_t)(cp & 3) * 4u;
                *(uint32_t*)(smb + off)         = pack_bf16(v.x, v.y);
                *(uint32_t*)(smb + PP_AL + off) = pack_bf16(v.x - hx, v.y - hy);
            }
        }
        {
#pragma unroll
            for (int it = 0; it < 16; it++) {
                int idx2 = it * 256 + tid;
                int r = idx2 >> 7, cp = idx2 & 127;
                float2 v = *(const float2*)(p2 + r * 256 + 2 * cp);
                int jj = cp >> 6, lcp = cp & 63;
                float hx = __bfloat162float(__float2bfloat16(v.x));
                float hy = __bfloat162float(__float2bfloat16(v.y));
                uint32_t off = sw_off(r, lcp >> 2) + (uint32_t)(lcp & 3) * 4u;
                char* bb = smb + PP_B + jj * 16384;
                *(uint32_t*)(bb + off)        = pack_bf16(v.x, v.y);
                *(uint32_t*)(bb + 8192 + off) = pack_bf16(v.x - hx, v.y - hy);
            }
        }
        __syncthreads();

#pragma unroll
        for (int j = 0; j < 2; j++) {
            float acc[2][4][4];
#pragma unroll
            for (int mr = 0; mr < 2; mr++)
#pragma unroll
                for (int nt = 0; nt < 4; nt++)
#pragma unroll
                    for (int i = 0; i < 4; i++) acc[mr][nt][i] = 0.f;

            const uint32_t Ao[3] = {0u, PP_AL, 0u};
            const uint32_t Bo[3] = {0u, 0u, 8192u};
#pragma unroll
            for (int pass = 0; pass < 3; pass++) {
                const uint32_t aB = sbase + Ao[pass];
                const uint32_t bB = sbase + PP_B + (uint32_t)j * 16384u + Bo[pass];
#pragma unroll
                for (int kc = 0; kc < 2; kc++) {
                    uint32_t a[2][4];
#pragma unroll
                    for (int mr = 0; mr < 2; mr++) {
                        int r = wr * 32 + mr * 16 + lq + (qq & 1) * 8;
                        int ci = kc * 2 + (qq >> 1);
                        ldsm_x4(a[mr], aB + sw_off(r, ci));
                    }
                    uint32_t bf[4][2];
#pragma unroll
                    for (int p = 0; p < 2; p++) {
                        int r = kc * 16 + lq + (qq & 1) * 8;
                        int ci = wc * 4 + p * 2 + (qq >> 1);
                        uint32_t t4r[4];
                        ldsm_x4_t(t4r, bB + sw_off(r, ci));
                        bf[2 * p][0] = t4r[0]; bf[2 * p][1] = t4r[1];
                        bf[2 * p + 1][0] = t4r[2]; bf[2 * p + 1][1] = t4r[3];
                    }
#pragma unroll
                    for (int mr = 0; mr < 2; mr++)
#pragma unroll
                        for (int nt = 0; nt < 4; nt++)
                            mma_bf16(acc[mr][nt], a[mr], bf[nt]);
                }
            }
#pragma unroll
            for (int mr = 0; mr < 2; mr++) {
#pragma unroll
                for (int half = 0; half < 2; half++) {
                    int i_row = wr * 32 + mr * 16 + half * 8 + grp;
                    int k = 2 * i_row + j;
#pragma unroll
                    for (int nt = 0; nt < 4; nt++) {
                        int c = wc * 32 + nt * 8 + tid4 * 2;
                        *(uint32_t*)(smb + PP_IMG + sw_off(k, c >> 3) + tid4 * 4) =
                            pack_h2(acc[mr][nt][half * 2 + 0], acc[mr][nt][half * 2 + 1]);
                    }
                }
            }
        }
        __syncthreads();

        float4* dst = (float4*)(g_Pimg + (size_t)(m * NN + n) * 16384);
        const float4* src = (const float4*)(smb + PP_IMG);
#pragma unroll
        for (int i = 0; i < 8; i++)
            dst[i * 256 + tid] = src[i * 256 + tid];
    }
}

// ---------------- fused kernel: 4 batches per block, 2 CTAs/SM, tensor attention ----------------
// smem bytes per CTA (106,496):
//  [A 0..24576)      96x128 fp16 swizzled (X during proj; Q image -> sO after)
//  [B 24576..57344)  P image during proj; W image (16KB) after
//  [K 57344..81920)  96x128 fp16 swizzled K image
//  [V 81920..106496) 96x128 fp16 swizzled V image
#define OFF_Bb 24576
#define OFF_K  57344
#define OFF_V  81920
#define SMEMF_TOTAL 106496

__global__ __launch_bounds__(256, 2) void fused_kernel(
    const float* __restrict__ query, const float* __restrict__ key_,
    const float* __restrict__ value,
    const float* __restrict__ outb,
    float* __restrict__ out, float* __restrict__ attn_out, int write_attn) {
    extern __shared__ float smf[];
    char* smb = (char*)smf;
    const uint32_t sbase = smem_u32(smb);

    const int n = blockIdx.x;
    const int b0 = blockIdx.y * G4;
    const int tid = threadIdx.x, wid = tid >> 5, lane = tid & 31;
    const int wr = wid >> 2, wc = wid & 3;        // warp grid 2(M) x 4(N)
    const int grp = lane >> 2, tid4 = lane & 3;
    const int lq = lane & 7, qq = lane >> 3;

    // ===== three projections (M=96 = 4 batches x 24), order k, v, q =====
    for (int mi = 0; mi < 3; mi++) {
        const int m = (mi + 1) % 3;               // 1, 2, 0
        if (mi) __syncthreads();
        // B: async copy P image in two 16KB halves (two commit groups)
        {
            const char* bs = (const char*)(g_Pimg + (size_t)(m * NN + n) * 16384);
            uint32_t bd = sbase + OFF_Bb;
#pragma unroll
            for (int i = 0; i < 4; i++) {
                int c = i * 256 + tid;
                CP_ASYNC16(bd + c * 16, bs + c * 16);
            }
            CP_COMMIT();
#pragma unroll
            for (int i = 4; i < 8; i++) {
                int c = i * 256 + tid;
                CP_ASYNC16(bd + c * 16, bs + c * 16);
            }
            CP_COMMIT();
        }
        // X: 96 rows x 128 fp32 -> fp16 swizzled, batched LDG (2 rounds of 6)
        {
            const float* x = (m == 0) ? query : ((m == 1) ? key_ : value);
#pragma unroll
            for (int rnd = 0; rnd < 2; rnd++) {
                float4 v[6];
#pragma unroll
                for (int it = 0; it < 6; it++) {
                    int idx = (rnd * 6 + it) * 256 + tid;
                    int r = idx >> 5, c4 = idx & 31;
                    int g = r / TT, t = r - g * TT;
                    v[it] = *(const float4*)(x + (((size_t)(b0 + g) * NN + n) * TT + t) * EE + 4 * c4);
                }
#pragma unroll
                for (int it = 0; it < 6; it++) {
                    int idx = (rnd * 6 + it) * 256 + tid;
                    int r = idx >> 5, c4 = idx & 31;
                    uint2 pk;
                    pk.x = pack_h2(v[it].x, v[it].y);
                    pk.y = pack_h2(v[it].z, v[it].w);
                    uint32_t off = sw_off(r, c4 >> 1) + (uint32_t)(c4 & 1) * 8u;
                    *(uint2*)(smb + off) = pk;
                }
            }
        }
        CP_WAIT1();           // B half0 resident
        __syncthreads();

        // GEMM 96 x 128 x 128, single pass fp16, split by B halves
        float acc[3][4][4];
#pragma unroll
        for (int mr = 0; mr < 3; mr++)
#pragma unroll
            for (int nt = 0; nt < 4; nt++)
#pragma unroll
                for (int i = 0; i < 4; i++) acc[mr][nt][i] = 0.f;

#pragma unroll
        for (int kc = 0; kc < 4; kc++) {
            uint32_t a[3][4];
#pragma unroll
            for (int mr = 0; mr < 3; mr++) {
                int r = wr * 48 + mr * 16 + lq + (qq & 1) * 8;
                int ci = kc * 2 + (qq >> 1);
                ldsm_x4(a[mr], sbase + sw_off(r, ci));
            }
            uint32_t bf[4][2];
#pragma unroll
            for (int p = 0; p < 2; p++) {
                int r = kc * 16 + lq + (qq & 1) * 8;
                int ci = wc * 4 + p * 2 + (qq >> 1);
                uint32_t t4r[4];
                ldsm_x4_t(t4r, sbase + OFF_Bb + sw_off(r, ci));
                bf[2 * p][0] = t4r[0]; bf[2 * p][1] = t4r[1];
                bf[2 * p + 1][0] = t4r[2]; bf[2 * p + 1][1] = t4r[3];
            }
#pragma unroll
            for (int mr = 0; mr < 3; mr++)
#pragma unroll
                for (int nt = 0; nt < 4; nt++)
                    mma_f16(acc[mr][nt], a[mr], bf[nt]);
        }
        CP_WAIT0();           // B half1 resident
        __syncthreads();
#pragma unroll
        for (int kc = 4; kc < 8; kc++) {
            uint32_t a[3][4];
#pragma unroll
            for (int mr = 0; mr < 3; mr++) {
                int r = wr * 48 + mr * 16 + lq + (qq & 1) * 8;
                int ci = kc * 2 + (qq >> 1);
                ldsm_x4(a[mr], sbase + sw_off(r, ci));
            }
            uint32_t bf[4][2];
#pragma unroll
            for (int p = 0; p < 2; p++) {
                int r = kc * 16 + lq + (qq & 1) * 8;
                int ci = wc * 4 + p * 2 + (qq >> 1);
                uint32_t t4r[4];
                ldsm_x4_t(t4r, sbase + OFF_Bb + sw_off(r, ci));
                bf[2 * p][0] = t4r[0]; bf[2 * p][1] = t4r[1];
                bf[2 * p + 1][0] = t4r[2]; bf[2 * p + 1][1] = t4r[3];
            }
#pragma unroll
            for (int mr = 0; mr < 3; mr++)
#pragma unroll
                for (int nt = 0; nt < 4; nt++)
                    mma_f16(acc[mr][nt], a[mr], bf[nt]);
        }

        // epilogue: relu -> swizzled image (A for q, K/V images for k/v)
        const uint32_t obase = (m == 0) ? 0u : ((m == 1) ? (uint32_t)OFF_K : (uint32_t)OFF_V);
        if (m == 0) __syncthreads();   // all mma reads of A (X_query) done before overwrite
#pragma unroll
        for (int mr = 0; mr < 3; mr++) {
#pragma unroll
            for (int half = 0; half < 2; half++) {
                int row = wr * 48 + mr * 16 + half * 8 + grp;
#pragma unroll
                for (int nt = 0; nt < 4; nt++) {
                    int col = wc * 32 + nt * 8 + tid4 * 2;
                    *(uint32_t*)(smb + obase + sw_off(row, col >> 3) + (col & 7) * 2) =
                        pack_h2(fmaxf(acc[mr][nt][half * 2 + 0], 0.f),
                                fmaxf(acc[mr][nt][half * 2 + 1], 0.f));
                }
            }
        }
    }
    __syncthreads();      // Q image + K,V images complete

    // W image async copy into B region (overlaps attention)
    {
        const char* ws = (const char*)g_Wimg;
#pragma unroll
        for (int i = 0; i < 4; i++) {
            int c = i * 256 + tid;
            CP_ASYNC16(sbase + OFF_Bb + c * 16, ws + c * 16);
        }
        CP_COMMIT();
    }

    // ===== tensor-core attention: warp = head, loop over 4 batches, sync-free =====
    const int h = wid;                            // 8 warps = 8 heads
    const int ci_h = h * 2 + (qq >> 1);
#pragma unroll 1
    for (int g = 0; g < G4; g++) {
        const int rowb = g * TT;
        const long bn = (long)(b0 + g) * NN + n;

        // Q A-frags (2 m-tiles) and K B-frags (3 n-tiles of s)
        uint32_t aq[2][4], kf[2][4];
#pragma unroll
        for (int mt = 0; mt < 2; mt++) {
            int r = rowb + mt * 16 + lq + (qq & 1) * 8;
            if (r > 95) r = 95;
            ldsm_x4(aq[mt], sbase + sw_off(r, ci_h));
        }
#pragma unroll
        for (int st = 0; st < 2; st++) {
            int r = rowb + st * 16 + lq + (qq & 1) * 8;
            if (r > 95) r = 95;
            ldsm_x4(kf[st], sbase + OFF_K + sw_off(r, ci_h));
        }
        uint32_t bK[3][2];
        bK[0][0] = kf[0][0]; bK[0][1] = kf[0][2];
        bK[1][0] = kf[0][1]; bK[1][1] = kf[0][3];
        bK[2][0] = kf[1][0]; bK[2][1] = kf[1][2];

        float S[2][3][4];
#pragma unroll
        for (int mt = 0; mt < 2; mt++)
#pragma unroll
            for (int nt = 0; nt < 3; nt++) {
#pragma unroll
                for (int i = 0; i < 4; i++) S[mt][nt][i] = 0.f;
                mma_f16(S[mt][nt], aq[mt], bK[nt]);
            }

        // softmax over s (cols), causal mask, in fragments
#pragma unroll
        for (int mt = 0; mt < 2; mt++) {
#pragma unroll
            for (int rh = 0; rh < 2; rh++) {
                int tloc = mt * 16 + grp + rh * 8;
                float x[3][2];
                float mx = -1e30f;
#pragma unroll
                for (int nt = 0; nt < 3; nt++)
#pragma unroll
                    for (int c = 0; c < 2; c++) {
                        int s = nt * 8 + 2 * tid4 + c;
                        bool ok = (tloc < TT) && (s <= tloc);
                        float v = ok ? S[mt][nt][rh * 2 + c] * 0.25f : -1e30f;
                        x[nt][c] = v;
                        mx = fmaxf(mx, v);
                    }
                mx = fmaxf(mx, __shfl_xor_sync(0xffffffffu, mx, 1));
                mx = fmaxf(mx, __shfl_xor_sync(0xffffffffu, mx, 2));
                float sum = 0.f;
#pragma unroll
                for (int nt = 0; nt < 3; nt++)
#pragma unroll
                    for (int c = 0; c < 2; c++) {
                        float e = (x[nt][c] > -1e29f) ? __expf(x[nt][c] - mx) : 0.f;
                        x[nt][c] = e;
                        sum += e;
                    }
                sum += __shfl_xor_sync(0xffffffffu, sum, 1);
                sum += __shfl_xor_sync(0xffffffffu, sum, 2);
                float inv = (sum > 0.f) ? (1.f / sum) : 0.f;
#pragma unroll
                for (int nt = 0; nt < 3; nt++)
#pragma unroll
                    for (int c = 0; c < 2; c++)
                        S[mt][nt][rh * 2 + c] = x[nt][c] * inv;
            }
        }

        // write attn probabilities (fp32, valid rows only)
        if (write_attn) {
#pragma unroll
            for (int vr = 0; vr < 3; vr++) {      // (mt,rh) in {(0,0),(0,1),(1,0)}
                int mt = (vr == 2) ? 1 : 0;
                int rh = (vr == 1) ? 1 : 0;
                int tloc = mt * 16 + grp + rh * 8;
                float* ab = attn_out + (((bn * HH) + h) * TT + tloc) * TT + 2 * tid4;
#pragma unroll
                for (int nt = 0; nt < 3; nt++)
                    *(float2*)(ab + nt * 8) =
                        make_float2(S[mt][nt][rh * 2 + 0], S[mt][nt][rh * 2 + 1]);
            }
        }

        // pack P to fp16 A-frags: [mt][kchunk][4]
        uint32_t pa[2][2][4];
#pragma unroll
        for (int mt = 0; mt < 2; mt++) {
            pa[mt][0][0] = pack_h2(S[mt][0][0], S[mt][0][1]);
            pa[mt][0][1] = pack_h2(S[mt][0][2], S[mt][0][3]);
            pa[mt][0][2] = pack_h2(S[mt][1][0], S[mt][1][1]);
            pa[mt][0][3] = pack_h2(S[mt][1][2], S[mt][1][3]);
            pa[mt][1][0] = pack_h2(S[mt][2][0], S[mt][2][1]);
            pa[mt][1][1] = pack_h2(S[mt][2][2], S[mt][2][3]);
            pa[mt][1][2] = 0u;
            pa[mt][1][3] = 0u;
        }

        // V B-frags (2 k-chunks x 2 d-tiles)
        uint32_t vf[2][4];
#pragma unroll
        for (int kc = 0; kc < 2; kc++) {
            int r = rowb + kc * 16 + lq + (qq & 1) * 8;
            if (r > 95) r = 95;
            ldsm_x4_t(vf[kc], sbase + OFF_V + sw_off(r, ci_h));
        }

        float O[2][2][4];
#pragma unroll
        for (int mt = 0; mt < 2; mt++)
#pragma unroll
            for (int ntd = 0; ntd < 2; ntd++) {
#pragma unroll
                for (int i = 0; i < 4; i++) O[mt][ntd][i] = 0.f;
#pragma unroll
                for (int kc = 0; kc < 2; kc++) {
                    uint32_t bv[2] = {vf[kc][ntd * 2], vf[kc][ntd * 2 + 1]};
                    mma_f16(O[mt][ntd], pa[mt][kc], bv);
                }
            }

        // sO as fp16 into A image (same cols this warp read Q from)
#pragma unroll
        for (int mt = 0; mt < 2; mt++) {
#pragma unroll
            for (int ntd = 0; ntd < 2; ntd++) {
                int row0 = rowb + mt * 16 + grp;
                int col = h * 16 + ntd * 8 + 2 * tid4;
                *(uint32_t*)(smb + sw_off(row0, col >> 3) + (col & 7) * 2) =
                    pack_h2(O[mt][ntd][0], O[mt][ntd][1]);
                if (mt == 0)
                    *(uint32_t*)(smb + sw_off(row0 + 8, col >> 3) + (col & 7) * 2) =
                        pack_h2(O[mt][ntd][2], O[mt][ntd][3]);
            }
        }
    }
    CP_WAIT0();
    __syncthreads();      // sO image complete, W image ready

    // ===== output projection: (96x128) @ (128x64) mma, bias+relu =====
    {
        float acc[3][2][4];
#pragma unroll
        for (int mr = 0; mr < 3; mr++)
#pragma unroll
            for (int nt = 0; nt < 2; nt++)
#pragma unroll
                for (int i = 0; i < 4; i++) acc[mr][nt][i] = 0.f;

#pragma unroll
        for (int kc = 0; kc < 8; kc++) {
            uint32_t a[3][4];
#pragma unroll
            for (int mr = 0; mr < 3; mr++) {
                int r = wr * 48 + mr * 16 + lq + (qq & 1) * 8;
                int ci = kc * 2 + (qq >> 1);
                ldsm_x4(a[mr], sbase + sw_off(r, ci));
            }
            uint32_t bf[2][2];
            {
                int r = kc * 16 + lq + (qq & 1) * 8;
                int ci = wc * 2 + (qq >> 1);
                uint32_t t4r[4];
                ldsm_x4_t(t4r, sbase + OFF_Bb + sw_off64(r, ci));
                bf[0][0] = t4r[0]; bf[0][1] = t4r[1];
                bf[1][0] = t4r[2]; bf[1][1] = t4r[3];
            }
#pragma unroll
            for (int mr = 0; mr < 3; mr++)
#pragma unroll
                for (int nt = 0; nt < 2; nt++)
                    mma_f16(acc[mr][nt], a[mr], bf[nt]);
        }

        float2 bias[2];
#pragma unroll
        for (int nt = 0; nt < 2; nt++) {
            int col = wc * 16 + nt * 8 + tid4 * 2;
            bias[nt] = make_float2(__ldg(outb + col), __ldg(outb + col + 1));
        }
#pragma unroll
        for (int mr = 0; mr < 3; mr++) {
#pragma unroll
            for (int half = 0; half < 2; half++) {
                int row = wr * 48 + mr * 16 + half * 8 + grp;
                int g = row / TT, t2 = row - g * TT;
                const long bn = (long)(b0 + g) * NN + n;
                float* op = out + ((bn * TT) + t2) * DMOUT;
#pragma unroll
                for (int nt = 0; nt < 2; nt++) {
                    int col = wc * 16 + nt * 8 + tid4 * 2;
                    *(float2*)(op + col) = make_float2(
                        fmaxf(acc[mr][nt][half * 2 + 0] + bias[nt].x, 0.f),
                        fmaxf(acc[mr][nt][half * 2 + 1] + bias[nt].y, 0.f));
                }
            }
        }
    }
}

// ---------------- launch ----------------
extern "C" void kernel_launch(void* const* d_in, const int* in_sizes, int n_in,
                              void* d_out, int out_size) {
    const float* query = (const float*)d_in[0];
    const float* key_  = (const float*)d_in[1];
    const float* value = (const float*)d_in[2];
    const float* qp1 = (const float*)d_in[4];
    const float* qp2 = (const float*)d_in[5];
    const float* kp1 = (const float*)d_in[6];
    const float* kp2 = (const float*)d_in[7];
    const float* vp1 = (const float*)d_in[8];
    const float* vp2 = (const float*)d_in[9];
    const float* outW = (const float*)d_in[10];
    const float* outb = (const float*)d_in[11];

    float* out = (float*)d_out;
    int write_attn = (out_size >= OUT_N + ATTN_N) ? 1 : 0;

    static int attr_done = 0;
    if (!attr_done) {
        cudaFuncSetAttribute(prep_P_kernel, cudaFuncAttributeMaxDynamicSharedMemorySize, PP_SMEM);
        cudaFuncSetAttribute(fused_kernel, cudaFuncAttributeMaxDynamicSharedMemorySize, SMEMF_TOTAL);
        attr_done = 1;
    }

    prep_P_kernel<<<NN, 256, PP_SMEM>>>(qp1, qp2, kp1, kp2, vp1, vp2, outW);
    fused_kernel<<<dim3(NN, BB / G4), 256, SMEMF_TOTAL>>>(
        query, key_, value, outb, out, out + OUT_N, write_attn);
}

// round 17
// speedup vs baseline: 1.1132x; 1.0237x over previous
#include <cuda_runtime.h>
#include <cuda_fp16.h>
#include <cuda_bf16.h>
#include <cstdint>

// ---------------- problem constants ----------------
#define BB 32
#define NN 207
#define TT 24
#define EE 128
#define HH 8
#define HD 16
#define DMOUT 64
#define MM 32
#define G4 4                         // batches per fused block

#define OUT_N (BB * NN * TT * DMOUT)
#define ATTN_N (BB * NN * HH * TT * TT)

// P images: per (m,n): 128 k-rows x 128 n-cols fp16, swizzled (32KB)
__device__ __align__(16) __half g_Pimg[(size_t)3 * NN * 16384];
// per-node readiness flags (zero-initialized; sticky across graph replays — see notes)
__device__ int g_flag[NN];

// ---------------- helpers ----------------
__device__ __forceinline__ uint32_t smem_u32(const void* p) {
    uint32_t a;
    asm("{ .reg .u64 t; cvta.to.shared.u64 t, %1; cvt.u32.u64 %0, t; }" : "=r"(a) : "l"(p));
    return a;
}
// swizzled byte offset: 256B rows, 16B chunks ci 0..15
__device__ __forceinline__ uint32_t sw_off(int r, int ci) {
    return (uint32_t)r * 256u + (uint32_t)((ci ^ (r & 7)) << 4);
}
// swizzled byte offset: 128B rows, 16B chunks ci 0..7
__device__ __forceinline__ uint32_t sw_off64(int r, int ci) {
    return (uint32_t)r * 128u + (uint32_t)((ci ^ (r & 7)) << 4);
}
__device__ __forceinline__ void ldsm_x4(uint32_t* r, uint32_t addr) {
    asm volatile("ldmatrix.sync.aligned.m8n8.x4.shared.b16 {%0,%1,%2,%3}, [%4];"
                 : "=r"(r[0]), "=r"(r[1]), "=r"(r[2]), "=r"(r[3]) : "r"(addr));
}
__device__ __forceinline__ void ldsm_x4_t(uint32_t* r, uint32_t addr) {
    asm volatile("ldmatrix.sync.aligned.m8n8.x4.trans.shared.b16 {%0,%1,%2,%3}, [%4];"
                 : "=r"(r[0]), "=r"(r[1]), "=r"(r[2]), "=r"(r[3]) : "r"(addr));
}
__device__ __forceinline__ void mma_f16(float* d, const uint32_t* a, const uint32_t* b) {
    asm volatile("mma.sync.aligned.m16n8k16.row.col.f32.f16.f16.f32 "
                 "{%0,%1,%2,%3}, {%4,%5,%6,%7}, {%8,%9}, {%0,%1,%2,%3};"
                 : "+f"(d[0]), "+f"(d[1]), "+f"(d[2]), "+f"(d[3])
                 : "r"(a[0]), "r"(a[1]), "r"(a[2]), "r"(a[3]), "r"(b[0]), "r"(b[1]));
}
__device__ __forceinline__ void mma_bf16(float* d, const uint32_t* a, const uint32_t* b) {
    asm volatile("mma.sync.aligned.m16n8k16.row.col.f32.bf16.bf16.f32 "
                 "{%0,%1,%2,%3}, {%4,%5,%6,%7}, {%8,%9}, {%0,%1,%2,%3};"
                 : "+f"(d[0]), "+f"(d[1]), "+f"(d[2]), "+f"(d[3])
                 : "r"(a[0]), "r"(a[1]), "r"(a[2]), "r"(a[3]), "r"(b[0]), "r"(b[1]));
}
#define CP_ASYNC16(dst, src) \
    asm volatile("cp.async.cg.shared.global [%0], [%1], 16;" :: "r"(dst), "l"(src))
#define CP_COMMIT() asm volatile("cp.async.commit_group;")
#define CP_WAIT0()  asm volatile("cp.async.wait_group 0;")
#define CP_WAIT1()  asm volatile("cp.async.wait_group 1;")

__device__ __forceinline__ uint32_t pack_bf16(float x, float y) {
    __nv_bfloat16 h0 = __float2bfloat16(x);
    __nv_bfloat16 h1 = __float2bfloat16(y);
    return (uint32_t)__bfloat16_as_ushort(h0) | ((uint32_t)__bfloat16_as_ushort(h1) << 16);
}
__device__ __forceinline__ uint32_t pack_h2(float x, float y) {
    __half2 h = __float22half2_rn(make_float2(x, y));
    return *(uint32_t*)&h;
}

// ---------------- smem layout (fused part; prep uses first 96KB) ----------------
#define PP_AL   16384
#define PP_B    32768
#define PP_IMG  65536
#define OFF_Bb 24576
#define OFF_K  57344
#define OFF_V  81920
#define SMEMF_TOTAL 106496

// ---------------- mega kernel: prep blocks (0..NN-1) + fused blocks ----------------
__global__ __launch_bounds__(256, 2) void mega_kernel(
    const float* __restrict__ query, const float* __restrict__ key_,
    const float* __restrict__ value,
    const float* __restrict__ qp1, const float* __restrict__ qp2,
    const float* __restrict__ kp1, const float* __restrict__ kp2,
    const float* __restrict__ vp1, const float* __restrict__ vp2,
    const float* __restrict__ outW, const float* __restrict__ outb,
    float* __restrict__ out, float* __restrict__ attn_out, int write_attn) {
    extern __shared__ float smf[];
    char* smb = (char*)smf;
    const uint32_t sbase = smem_u32(smb);

    const int tid = threadIdx.x, wid = tid >> 5, lane = tid & 31;
    const int grp = lane >> 2, tid4 = lane & 3;
    const int lq = lane & 7, qq = lane >> 3;

    if (blockIdx.x < NN) {
        // ================= PREP PATH: build node n's three P images =================
        const int n = blockIdx.x;
        const int wr = wid >> 2, wc = wid & 3;   // 2(M) x 4(N)

        for (int m = 0; m < 3; m++) {
            if (m) __syncthreads();
            const float* p1 = (m == 0) ? qp1 : ((m == 1) ? kp1 : vp1);
            const float* p2 = (m == 0) ? qp2 : ((m == 1) ? kp2 : vp2);

            {
                const float* p1b = p1 + (size_t)n * 2048;
#pragma unroll
                for (int it = 0; it < 4; it++) {
                    int idx2 = it * 256 + tid;
                    int r = idx2 >> 4, cp = idx2 & 15;
                    float2 v = *(const float2*)(p1b + r * 32 + 2 * cp);
                    float hx = __bfloat162float(__float2bfloat16(v.x));
                    float hy = __bfloat162float(__float2bfloat16(v.y));
                    uint32_t off = sw_off(r, cp >> 2) + (uint32_t)(cp & 3) * 4u;
                    *(uint32_t*)(smb + off)         = pack_bf16(v.x, v.y);
                    *(uint32_t*)(smb + PP_AL + off) = pack_bf16(v.x - hx, v.y - hy);
                }
            }
            {
#pragma unroll
                for (int it = 0; it < 16; it++) {
                    int idx2 = it * 256 + tid;
                    int r = idx2 >> 7, cp = idx2 & 127;
                    float2 v = *(const float2*)(p2 + r * 256 + 2 * cp);
                    int jj = cp >> 6, lcp = cp & 63;
                    float hx = __bfloat162float(__float2bfloat16(v.x));
                    float hy = __bfloat162float(__float2bfloat16(v.y));
                    uint32_t off = sw_off(r, lcp >> 2) + (uint32_t)(lcp & 3) * 4u;
                    char* bb = smb + PP_B + jj * 16384;
                    *(uint32_t*)(bb + off)        = pack_bf16(v.x, v.y);
                    *(uint32_t*)(bb + 8192 + off) = pack_bf16(v.x - hx, v.y - hy);
                }
            }
            __syncthreads();

#pragma unroll
            for (int j = 0; j < 2; j++) {
                float acc[2][4][4];
#pragma unroll
                for (int mr = 0; mr < 2; mr++)
#pragma unroll
                    for (int nt = 0; nt < 4; nt++)
#pragma unroll
                        for (int i = 0; i < 4; i++) acc[mr][nt][i] = 0.f;

                const uint32_t Ao[3] = {0u, PP_AL, 0u};
                const uint32_t Bo[3] = {0u, 0u, 8192u};
#pragma unroll
                for (int pass = 0; pass < 3; pass++) {
                    const uint32_t aB = sbase + Ao[pass];
                    const uint32_t bB = sbase + PP_B + (uint32_t)j * 16384u + Bo[pass];
#pragma unroll
                    for (int kc = 0; kc < 2; kc++) {
                        uint32_t a[2][4];
#pragma unroll
                        for (int mr = 0; mr < 2; mr++) {
                            int r = wr * 32 + mr * 16 + lq + (qq & 1) * 8;
                            int ci = kc * 2 + (qq >> 1);
                            ldsm_x4(a[mr], aB + sw_off(r, ci));
                        }
                        uint32_t bf[4][2];
#pragma unroll
                        for (int p = 0; p < 2; p++) {
                            int r = kc * 16 + lq + (qq & 1) * 8;
                            int ci = wc * 4 + p * 2 + (qq >> 1);
                            uint32_t t4r[4];
                            ldsm_x4_t(t4r, bB + sw_off(r, ci));
                            bf[2 * p][0] = t4r[0]; bf[2 * p][1] = t4r[1];
                            bf[2 * p + 1][0] = t4r[2]; bf[2 * p + 1][1] = t4r[3];
                        }
#pragma unroll
                        for (int mr = 0; mr < 2; mr++)
#pragma unroll
                            for (int nt = 0; nt < 4; nt++)
                                mma_bf16(acc[mr][nt], a[mr], bf[nt]);
                    }
                }
#pragma unroll
                for (int mr = 0; mr < 2; mr++) {
#pragma unroll
                    for (int half = 0; half < 2; half++) {
                        int i_row = wr * 32 + mr * 16 + half * 8 + grp;
                        int k = 2 * i_row + j;
#pragma unroll
                        for (int nt = 0; nt < 4; nt++) {
                            int c = wc * 32 + nt * 8 + tid4 * 2;
                            *(uint32_t*)(smb + PP_IMG + sw_off(k, c >> 3) + tid4 * 4) =
                                pack_h2(acc[mr][nt][half * 2 + 0], acc[mr][nt][half * 2 + 1]);
                        }
                    }
                }
            }
            __syncthreads();

            float4* dst = (float4*)(g_Pimg + (size_t)(m * NN + n) * 16384);
            const float4* src = (const float4*)(smb + PP_IMG);
#pragma unroll
            for (int i = 0; i < 8; i++)
                dst[i * 256 + tid] = src[i * 256 + tid];
        }
        __threadfence();
        __syncthreads();
        if (tid == 0) atomicExch(&g_flag[n], 1);
        return;
    }

    // ================= FUSED PATH =================
    const int fidx = blockIdx.x - NN;
    const int n = fidx % NN;
    const int b0 = (fidx / NN) * G4;
    const int wr = wid >> 2, wc = wid & 3;        // warp grid 2(M) x 4(N)

    // wait until node n's P images are ready (no-op after first pass / on replays)
    if (tid == 0) {
        while (atomicAdd(&g_flag[n], 0) == 0) { __nanosleep(64); }
    }
    __syncthreads();

    // ===== three projections (M=96 = 4 batches x 24), order k, v, q =====
    for (int mi = 0; mi < 3; mi++) {
        const int m = (mi + 1) % 3;               // 1, 2, 0
        if (mi) __syncthreads();
        // B: async copy P image in two 16KB halves (two commit groups)
        {
            const char* bs = (const char*)(g_Pimg + (size_t)(m * NN + n) * 16384);
            uint32_t bd = sbase + OFF_Bb;
#pragma unroll
            for (int i = 0; i < 4; i++) {
                int c = i * 256 + tid;
                CP_ASYNC16(bd + c * 16, bs + c * 16);
            }
            CP_COMMIT();
#pragma unroll
            for (int i = 4; i < 8; i++) {
                int c = i * 256 + tid;
                CP_ASYNC16(bd + c * 16, bs + c * 16);
            }
            CP_COMMIT();
        }
        // X: 96 rows x 128 fp32 -> fp16 swizzled, batched LDG (2 rounds of 6)
        {
            const float* x = (m == 0) ? query : ((m == 1) ? key_ : value);
#pragma unroll
            for (int rnd = 0; rnd < 2; rnd++) {
                float4 v[6];
#pragma unroll
                for (int it = 0; it < 6; it++) {
                    int idx = (rnd * 6 + it) * 256 + tid;
                    int r = idx >> 5, c4 = idx & 31;
                    int g = r / TT, t = r - g * TT;
                    v[it] = *(const float4*)(x + (((size_t)(b0 + g) * NN + n) * TT + t) * EE + 4 * c4);
                }
#pragma unroll
                for (int it = 0; it < 6; it++) {
                    int idx = (rnd * 6 + it) * 256 + tid;
                    int r = idx >> 5, c4 = idx & 31;
                    uint2 pk;
                    pk.x = pack_h2(v[it].x, v[it].y);
                    pk.y = pack_h2(v[it].z, v[it].w);
                    uint32_t off = sw_off(r, c4 >> 1) + (uint32_t)(c4 & 1) * 8u;
                    *(uint2*)(smb + off) = pk;
                }
            }
        }
        CP_WAIT1();           // B half0 resident
        __syncthreads();

        // GEMM 96 x 128 x 128, single pass fp16, split by B halves
        float acc[3][4][4];
#pragma unroll
        for (int mr = 0; mr < 3; mr++)
#pragma unroll
            for (int nt = 0; nt < 4; nt++)
#pragma unroll
                for (int i = 0; i < 4; i++) acc[mr][nt][i] = 0.f;

#pragma unroll
        for (int kc = 0; kc < 4; kc++) {
            uint32_t a[3][4];
#pragma unroll
            for (int mr = 0; mr < 3; mr++) {
                int r = wr * 48 + mr * 16 + lq + (qq & 1) * 8;
                int ci = kc * 2 + (qq >> 1);
                ldsm_x4(a[mr], sbase + sw_off(r, ci));
            }
            uint32_t bf[4][2];
#pragma unroll
            for (int p = 0; p < 2; p++) {
                int r = kc * 16 + lq + (qq & 1) * 8;
                int ci = wc * 4 + p * 2 + (qq >> 1);
                uint32_t t4r[4];
                ldsm_x4_t(t4r, sbase + OFF_Bb + sw_off(r, ci));
                bf[2 * p][0] = t4r[0]; bf[2 * p][1] = t4r[1];
                bf[2 * p + 1][0] = t4r[2]; bf[2 * p + 1][1] = t4r[3];
            }
#pragma unroll
            for (int mr = 0; mr < 3; mr++)
#pragma unroll
                for (int nt = 0; nt < 4; nt++)
                    mma_f16(acc[mr][nt], a[mr], bf[nt]);
        }
        CP_WAIT0();           // B half1 resident
        __syncthreads();
#pragma unroll
        for (int kc = 4; kc < 8; kc++) {
            uint32_t a[3][4];
#pragma unroll
            for (int mr = 0; mr < 3; mr++) {
                int r = wr * 48 + mr * 16 + lq + (qq & 1) * 8;
                int ci = kc * 2 + (qq >> 1);
                ldsm_x4(a[mr], sbase + sw_off(r, ci));
            }
            uint32_t bf[4][2];
#pragma unroll
            for (int p = 0; p < 2; p++) {
                int r = kc * 16 + lq + (qq & 1) * 8;
                int ci = wc * 4 + p * 2 + (qq >> 1);
                uint32_t t4r[4];
                ldsm_x4_t(t4r, sbase + OFF_Bb + sw_off(r, ci));
                bf[2 * p][0] = t4r[0]; bf[2 * p][1] = t4r[1];
                bf[2 * p + 1][0] = t4r[2]; bf[2 * p + 1][1] = t4r[3];
            }
#pragma unroll
            for (int mr = 0; mr < 3; mr++)
#pragma unroll
                for (int nt = 0; nt < 4; nt++)
                    mma_f16(acc[mr][nt], a[mr], bf[nt]);
        }

        // epilogue: relu -> swizzled image (A for q, K/V images for k/v)
        const uint32_t obase = (m == 0) ? 0u : ((m == 1) ? (uint32_t)OFF_K : (uint32_t)OFF_V);
        if (m == 0) __syncthreads();   // all mma reads of A (X_query) done before overwrite
#pragma unroll
        for (int mr = 0; mr < 3; mr++) {
#pragma unroll
            for (int half = 0; half < 2; half++) {
                int row = wr * 48 + mr * 16 + half * 8 + grp;
#pragma unroll
                for (int nt = 0; nt < 4; nt++) {
                    int col = wc * 32 + nt * 8 + tid4 * 2;
                    *(uint32_t*)(smb + obase + sw_off(row, col >> 3) + (col & 7) * 2) =
                        pack_h2(fmaxf(acc[mr][nt][half * 2 + 0], 0.f),
                                fmaxf(acc[mr][nt][half * 2 + 1], 0.f));
                }
            }
        }
    }
    __syncthreads();      // Q image + K,V images complete; B region free

    // W image: build directly from outW (fp32, L2-hot) into B region
    {
#pragma unroll
        for (int it = 0; it < 16; it++) {
            int idx = it * 256 + tid;          // 4096 float2 jobs
            int k = idx >> 5, n2 = idx & 31;
            float2 v = *(const float2*)(outW + k * DMOUT + 2 * n2);
            uint32_t off = sw_off64(k, n2 >> 2) + (uint32_t)(n2 & 3) * 4u;
            *(uint32_t*)(smb + OFF_Bb + off) = pack_h2(v.x, v.y);
        }
    }

    // ===== tensor-core attention: warp = head, loop over 4 batches, sync-free =====
    const int h = wid;                            // 8 warps = 8 heads
    const int ci_h = h * 2 + (qq >> 1);
#pragma unroll 1
    for (int g = 0; g < G4; g++) {
        const int rowb = g * TT;
        const long bn = (long)(b0 + g) * NN + n;

        uint32_t aq[2][4], kf[2][4];
#pragma unroll
        for (int mt = 0; mt < 2; mt++) {
            int r = rowb + mt * 16 + lq + (qq & 1) * 8;
            if (r > 95) r = 95;
            ldsm_x4(aq[mt], sbase + sw_off(r, ci_h));
        }
#pragma unroll
        for (int st = 0; st < 2; st++) {
            int r = rowb + st * 16 + lq + (qq & 1) * 8;
            if (r > 95) r = 95;
            ldsm_x4(kf[st], sbase + OFF_K + sw_off(r, ci_h));
        }
        uint32_t bK[3][2];
        bK[0][0] = kf[0][0]; bK[0][1] = kf[0][2];
        bK[1][0] = kf[0][1]; bK[1][1] = kf[0][3];
        bK[2][0] = kf[1][0]; bK[2][1] = kf[1][2];

        float S[2][3][4];
#pragma unroll
        for (int mt = 0; mt < 2; mt++)
#pragma unroll
            for (int nt = 0; nt < 3; nt++) {
#pragma unroll
                for (int i = 0; i < 4; i++) S[mt][nt][i] = 0.f;
                mma_f16(S[mt][nt], aq[mt], bK[nt]);
            }

        // softmax over s (cols), causal mask, in fragments
#pragma unroll
        for (int mt = 0; mt < 2; mt++) {
#pragma unroll
            for (int rh = 0; rh < 2; rh++) {
                int tloc = mt * 16 + grp + rh * 8;
                float x[3][2];
                float mx = -1e30f;
#pragma unroll
                for (int nt = 0; nt < 3; nt++)
#pragma unroll
                    for (int c = 0; c < 2; c++) {
                        int s = nt * 8 + 2 * tid4 + c;
                        bool ok = (tloc < TT) && (s <= tloc);
                        float v = ok ? S[mt][nt][rh * 2 + c] * 0.25f : -1e30f;
                        x[nt][c] = v;
                        mx = fmaxf(mx, v);
                    }
                mx = fmaxf(mx, __shfl_xor_sync(0xffffffffu, mx, 1));
                mx = fmaxf(mx, __shfl_xor_sync(0xffffffffu, mx, 2));
                float sum = 0.f;
#pragma unroll
                for (int nt = 0; nt < 3; nt++)
#pragma unroll
                    for (int c = 0; c < 2; c++) {
                        float e = (x[nt][c] > -1e29f) ? __expf(x[nt][c] - mx) : 0.f;
                        x[nt][c] = e;
                        sum += e;
                    }
                sum += __shfl_xor_sync(0xffffffffu, sum, 1);
                sum += __shfl_xor_sync(0xffffffffu, sum, 2);
                float inv = (sum > 0.f) ? (1.f / sum) : 0.f;
#pragma unroll
                for (int nt = 0; nt < 3; nt++)
#pragma unroll
                    for (int c = 0; c < 2; c++)
                        S[mt][nt][rh * 2 + c] = x[nt][c] * inv;
            }
        }

        if (write_attn) {
#pragma unroll
            for (int vr = 0; vr < 3; vr++) {      // (mt,rh) in {(0,0),(0,1),(1,0)}
                int mt = (vr == 2) ? 1 : 0;
                int rh = (vr == 1) ? 1 : 0;
                int tloc = mt * 16 + grp + rh * 8;
                float* ab = attn_out + (((bn * HH) + h) * TT + tloc) * TT + 2 * tid4;
#pragma unroll
                for (int nt = 0; nt < 3; nt++)
                    *(float2*)(ab + nt * 8) =
                        make_float2(S[mt][nt][rh * 2 + 0], S[mt][nt][rh * 2 + 1]);
            }
        }

        // pack P to fp16 A-frags
        uint32_t pa[2][2][4];
#pragma unroll
        for (int mt = 0; mt < 2; mt++) {
            pa[mt][0][0] = pack_h2(S[mt][0][0], S[mt][0][1]);
            pa[mt][0][1] = pack_h2(S[mt][0][2], S[mt][0][3]);
            pa[mt][0][2] = pack_h2(S[mt][1][0], S[mt][1][1]);
            pa[mt][0][3] = pack_h2(S[mt][1][2], S[mt][1][3]);
            pa[mt][1][0] = pack_h2(S[mt][2][0], S[mt][2][1]);
            pa[mt][1][1] = pack_h2(S[mt][2][2], S[mt][2][3]);
            pa[mt][1][2] = 0u;
            pa[mt][1][3] = 0u;
        }

        uint32_t vf[2][4];
#pragma unroll
        for (int kc = 0; kc < 2; kc++) {
            int r = rowb + kc * 16 + lq + (qq & 1) * 8;
            if (r > 95) r = 95;
            ldsm_x4_t(vf[kc], sbase + OFF_V + sw_off(r, ci_h));
        }

        float O[2][2][4];
#pragma unroll
        for (int mt = 0; mt < 2; mt++)
#pragma unroll
            for (int ntd = 0; ntd < 2; ntd++) {
#pragma unroll
                for (int i = 0; i < 4; i++) O[mt][ntd][i] = 0.f;
#pragma unroll
                for (int kc = 0; kc < 2; kc++) {
                    uint32_t bv[2] = {vf[kc][ntd * 2], vf[kc][ntd * 2 + 1]};
                    mma_f16(O[mt][ntd], pa[mt][kc], bv);
                }
            }

        // sO as fp16 into A image (same cols this warp read Q from)
#pragma unroll
        for (int mt = 0; mt < 2; mt++) {
#pragma unroll
            for (int ntd = 0; ntd < 2; ntd++) {
                int row0 = rowb + mt * 16 + grp;
                int col = h * 16 + ntd * 8 + 2 * tid4;
                *(uint32_t*)(smb + sw_off(row0, col >> 3) + (col & 7) * 2) =
                    pack_h2(O[mt][ntd][0], O[mt][ntd][1]);
                if (mt == 0)
                    *(uint32_t*)(smb + sw_off(row0 + 8, col >> 3) + (col & 7) * 2) =
                        pack_h2(O[mt][ntd][2], O[mt][ntd][3]);
            }
        }
    }
    __syncthreads();      // sO image complete, W image visible

    // ===== output projection: (96x128) @ (128x64) mma, bias+relu =====
    {
        float acc[3][2][4];
#pragma unroll
        for (int mr = 0; mr < 3; mr++)
#pragma unroll
            for (int nt = 0; nt < 2; nt++)
#pragma unroll
                for (int i = 0; i < 4; i++) acc[mr][nt][i] = 0.f;

#pragma unroll
        for (int kc = 0; kc < 8; kc++) {
            uint32_t a[3][4];
#pragma unroll
            for (int mr = 0; mr < 3; mr++) {
                int r = wr * 48 + mr * 16 + lq + (qq & 1) * 8;
                int ci = kc * 2 + (qq >> 1);
                ldsm_x4(a[mr], sbase + sw_off(r, ci));
            }
            uint32_t bf[2][2];
            {
                int r = kc * 16 + lq + (qq & 1) * 8;
                int ci = wc * 2 + (qq >> 1);
                uint32_t t4r[4];
                ldsm_x4_t(t4r, sbase + OFF_Bb + sw_off64(r, ci));
                bf[0][0] = t4r[0]; bf[0][1] = t4r[1];
                bf[1][0] = t4r[2]; bf[1][1] = t4r[3];
            }
#pragma unroll
            for (int mr = 0; mr < 3; mr++)
#pragma unroll
                for (int nt = 0; nt < 2; nt++)
                    mma_f16(acc[mr][nt], a[mr], bf[nt]);
        }

        float2 bias[2];
#pragma unroll
        for (int nt = 0; nt < 2; nt++) {
            int col = wc * 16 + nt * 8 + tid4 * 2;
            bias[nt] = make_float2(__ldg(outb + col), __ldg(outb + col + 1));
        }
#pragma unroll
        for (int mr = 0; mr < 3; mr++) {
#pragma unroll
            for (int half = 0; half < 2; half++) {
                int row = wr * 48 + mr * 16 + half * 8 + grp;
                int g = row / TT, t2 = row - g * TT;
                const long bn = (long)(b0 + g) * NN + n;
                float* op = out + ((bn * TT) + t2) * DMOUT;
#pragma unroll
                for (int nt = 0; nt < 2; nt++) {
                    int col = wc * 16 + nt * 8 + tid4 * 2;
                    *(float2*)(op + col) = make_float2(
                        fmaxf(acc[mr][nt][half * 2 + 0] + bias[nt].x, 0.f),
                        fmaxf(acc[mr][nt][half * 2 + 1] + bias[nt].y, 0.f));
                }
            }
        }
    }
}

// ---------------- launch ----------------
extern "C" void kernel_launch(void* const* d_in, const int* in_sizes, int n_in,
                              void* d_out, int out_size) {
    const float* query = (const float*)d_in[0];
    const float* key_  = (const float*)d_in[1];
    const float* value = (const float*)d_in[2];
    const float* qp1 = (const float*)d_in[4];
    const float* qp2 = (const float*)d_in[5];
    const float* kp1 = (const float*)d_in[6];
    const float* kp2 = (const float*)d_in[7];
    const float* vp1 = (const float*)d_in[8];
    const float* vp2 = (const float*)d_in[9];
    const float* outW = (const float*)d_in[10];
    const float* outb = (const float*)d_in[11];

    float* out = (float*)d_out;
    int write_attn = (out_size >= OUT_N + ATTN_N) ? 1 : 0;

    static int attr_done = 0;
    if (!attr_done) {
        cudaFuncSetAttribute(mega_kernel, cudaFuncAttributeMaxDynamicSharedMemorySize, SMEMF_TOTAL);
        attr_done = 1;
    }

    mega_kernel<<<NN + NN * (BB / G4), 256, SMEMF_TOTAL>>>(
        query, key_, value, qp1, qp2, kp1, kp2, vp1, vp2, outW, outb,
        out, out + OUT_N, write_attn);
}